// round 1
// baseline (speedup 1.0000x reference)
#include <cuda_runtime.h>
#include <math.h>

#define BB 2
#define SS 2048
#define DD 1024
#define HH 16
#define DH 64
#define MM (BB * SS)   // 4096

// Scratch: [B,H,S,Dh] for q,k,v ; [B,S,D] for attention output
__device__ float g_q[BB * HH * SS * DH];
__device__ float g_k[BB * HH * SS * DH];
__device__ float g_v[BB * HH * SS * DH];
__device__ float g_att[BB * SS * DD];

// ---------------------------------------------------------------------------
// NT GEMM: C[m,n] = sum_k A[m,k] * W[n,k] (+bias). 128x128 tile, 256 thr, 8x8.
// mode 0/1/2: A = x, out -> g_q/g_k/g_v in [B,H,S,Dh] layout
// mode 3:     A = g_att, out -> Cext ([B,S,D]) with bias
// ---------------------------------------------------------------------------
__global__ void __launch_bounds__(256) gemm128(const float* __restrict__ A,
                                               const float* __restrict__ W,
                                               const float* __restrict__ bias,
                                               float* __restrict__ Cext,
                                               int mode) {
    __shared__ float As[8][128];
    __shared__ float Bs[8][128];

    const int t  = threadIdx.x;
    const int m0 = blockIdx.y * 128;
    const int n0 = blockIdx.x * 128;
    const int lr = t >> 1;          // 0..127
    const int lk = (t & 1) * 4;     // 0 or 4
    const int tm = t >> 4;          // 0..15
    const int tn = t & 15;          // 0..15

    const float* Asrc = (mode == 3) ? g_att : A;
    float* C = (mode == 0) ? g_q : (mode == 1) ? g_k : (mode == 2) ? g_v : Cext;

    const float* Ap = Asrc + (size_t)(m0 + lr) * 1024 + lk;
    const float* Wp = W    + (size_t)(n0 + lr) * 1024 + lk;

    float c[8][8];
#pragma unroll
    for (int i = 0; i < 8; i++)
#pragma unroll
        for (int j = 0; j < 8; j++) c[i][j] = 0.f;

    for (int k0 = 0; k0 < 1024; k0 += 8) {
        float4 a = *(const float4*)(Ap + k0);
        float4 b = *(const float4*)(Wp + k0);
        __syncthreads();
        As[lk + 0][lr] = a.x; As[lk + 1][lr] = a.y;
        As[lk + 2][lr] = a.z; As[lk + 3][lr] = a.w;
        Bs[lk + 0][lr] = b.x; Bs[lk + 1][lr] = b.y;
        Bs[lk + 2][lr] = b.z; Bs[lk + 3][lr] = b.w;
        __syncthreads();

#pragma unroll
        for (int kk = 0; kk < 8; kk++) {
            float ar[8], br[8];
            float4 t0 = *(const float4*)&As[kk][tm * 8];
            float4 t1 = *(const float4*)&As[kk][tm * 8 + 4];
            ar[0] = t0.x; ar[1] = t0.y; ar[2] = t0.z; ar[3] = t0.w;
            ar[4] = t1.x; ar[5] = t1.y; ar[6] = t1.z; ar[7] = t1.w;
            float4 u0 = *(const float4*)&Bs[kk][tn * 8];
            float4 u1 = *(const float4*)&Bs[kk][tn * 8 + 4];
            br[0] = u0.x; br[1] = u0.y; br[2] = u0.z; br[3] = u0.w;
            br[4] = u1.x; br[5] = u1.y; br[6] = u1.z; br[7] = u1.w;
#pragma unroll
            for (int i = 0; i < 8; i++)
#pragma unroll
                for (int j = 0; j < 8; j++) c[i][j] = fmaf(ar[i], br[j], c[i][j]);
        }
    }

    if (mode == 3) {
#pragma unroll
        for (int i = 0; i < 8; i++) {
            int m = m0 + tm * 8 + i;
            int n = n0 + tn * 8;
            float* orow = C + (size_t)m * 1024 + n;
            float4 v0 = make_float4(c[i][0] + bias[n + 0], c[i][1] + bias[n + 1],
                                    c[i][2] + bias[n + 2], c[i][3] + bias[n + 3]);
            float4 v1 = make_float4(c[i][4] + bias[n + 4], c[i][5] + bias[n + 5],
                                    c[i][6] + bias[n + 6], c[i][7] + bias[n + 7]);
            *(float4*)(orow)     = v0;
            *(float4*)(orow + 4) = v1;
        }
    } else {
#pragma unroll
        for (int i = 0; i < 8; i++) {
            int m = m0 + tm * 8 + i;
            int b = m >> 11;        // m / 2048
            int s = m & 2047;
            int n = n0 + tn * 8;
            int h = n >> 6;         // n / 64
            int dh = n & 63;
            float* orow = C + (size_t)((b * HH + h) * SS + s) * DH + dh;
            float4 v0 = make_float4(c[i][0], c[i][1], c[i][2], c[i][3]);
            float4 v1 = make_float4(c[i][4], c[i][5], c[i][6], c[i][7]);
            *(float4*)(orow)     = v0;
            *(float4*)(orow + 4) = v1;
        }
    }
}

// ---------------------------------------------------------------------------
// Flash attention: 1 query row per thread, 128 rows/block, 32-key tiles.
// Reads g_q/g_k/g_v [B,H,S,Dh]; writes g_att [B,S,D].
// ---------------------------------------------------------------------------
__global__ void __launch_bounds__(128) attn128() {
    const int b = blockIdx.z;
    const int h = blockIdx.y;
    const int t = threadIdx.x;
    const int row = blockIdx.x * 128 + t;

    const size_t bh = (size_t)(b * HH + h) * SS;
    const float4* qrow = (const float4*)(g_q + (bh + row) * DH);
    const float4* Kb = (const float4*)(g_k + bh * DH);
    const float4* Vb = (const float4*)(g_v + bh * DH);

    float4 qr[16];
#pragma unroll
    for (int c = 0; c < 16; c++) {
        float4 q4 = qrow[c];
        qr[c] = make_float4(q4.x * 0.125f, q4.y * 0.125f, q4.z * 0.125f, q4.w * 0.125f);
    }
    float4 acc[16];
#pragma unroll
    for (int c = 0; c < 16; c++) acc[c] = make_float4(0.f, 0.f, 0.f, 0.f);

    float mi = -1e30f, li = 0.f;

    __shared__ float4 Ks[32][16];
    __shared__ float4 Vs[32][16];

    for (int kt = 0; kt < SS; kt += 32) {
        __syncthreads();
#pragma unroll
        for (int i = 0; i < 4; i++) {
            int idx = t + i * 128;
            int r = idx >> 4;
            int cc = idx & 15;
            Ks[r][cc] = Kb[(size_t)(kt + r) * 16 + cc];
            Vs[r][cc] = Vb[(size_t)(kt + r) * 16 + cc];
        }
        __syncthreads();

        float sc[32];
        float tmax = mi;
#pragma unroll
        for (int j = 0; j < 32; j++) {
            float4 s4 = make_float4(0.f, 0.f, 0.f, 0.f);
#pragma unroll
            for (int cc = 0; cc < 16; cc++) {
                float4 kk = Ks[j][cc];
                s4.x = fmaf(qr[cc].x, kk.x, s4.x);
                s4.y = fmaf(qr[cc].y, kk.y, s4.y);
                s4.z = fmaf(qr[cc].z, kk.z, s4.z);
                s4.w = fmaf(qr[cc].w, kk.w, s4.w);
            }
            float s = (s4.x + s4.y) + (s4.z + s4.w);
            sc[j] = s;
            tmax = fmaxf(tmax, s);
        }
        float corr = __expf(mi - tmax);
        mi = tmax;
        li *= corr;
#pragma unroll
        for (int cc = 0; cc < 16; cc++) {
            acc[cc].x *= corr; acc[cc].y *= corr;
            acc[cc].z *= corr; acc[cc].w *= corr;
        }
#pragma unroll
        for (int j = 0; j < 32; j++) {
            float p = __expf(sc[j] - mi);
            li += p;
#pragma unroll
            for (int cc = 0; cc < 16; cc++) {
                float4 vv = Vs[j][cc];
                acc[cc].x = fmaf(p, vv.x, acc[cc].x);
                acc[cc].y = fmaf(p, vv.y, acc[cc].y);
                acc[cc].z = fmaf(p, vv.z, acc[cc].z);
                acc[cc].w = fmaf(p, vv.w, acc[cc].w);
            }
        }
    }

    float inv = 1.f / li;
    float4* orow = (float4*)(g_att + ((size_t)b * SS + row) * DD + h * DH);
#pragma unroll
    for (int cc = 0; cc < 16; cc++) {
        orow[cc] = make_float4(acc[cc].x * inv, acc[cc].y * inv,
                               acc[cc].z * inv, acc[cc].w * inv);
    }
}

extern "C" void kernel_launch(void* const* d_in, const int* in_sizes, int n_in,
                              void* d_out, int out_size) {
    const float* x  = (const float*)d_in[0];
    const float* wq = (const float*)d_in[1];
    const float* wk = (const float*)d_in[2];
    const float* wv = (const float*)d_in[3];
    const float* wo = (const float*)d_in[4];
    const float* bo = (const float*)d_in[5];
    float* out = (float*)d_out;

    dim3 gg(DD / 128, MM / 128);   // (8, 32)
    gemm128<<<gg, 256>>>(x, wq, nullptr, nullptr, 0);
    gemm128<<<gg, 256>>>(x, wk, nullptr, nullptr, 1);
    gemm128<<<gg, 256>>>(x, wv, nullptr, nullptr, 2);

    dim3 ga(SS / 128, HH, BB);     // (16, 16, 2)
    attn128<<<ga, 128>>>();

    gemm128<<<gg, 256>>>(nullptr, wo, bo, out, 3);
}

// round 3
// speedup vs baseline: 1.1821x; 1.1821x over previous
#include <cuda_runtime.h>
#include <math.h>

#define BB 2
#define SS 2048
#define DD 1024
#define HH 16
#define DH 64
#define MM (BB * SS)   // 4096

// Scratch: [B,H,S,Dh] for q,k,v ; [B,S,D] for attention output
__device__ float g_q[BB * HH * SS * DH];
__device__ float g_k[BB * HH * SS * DH];
__device__ float g_v[BB * HH * SS * DH];
__device__ float g_att[BB * SS * DD];

// ---------------------------------------------------------------------------
// 3xTF32 split helpers + mma.sync wrapper (m16n8k8 row.col f32.tf32)
// ---------------------------------------------------------------------------
__device__ __forceinline__ void split_tf32(float x, unsigned& hi, unsigned& lo) {
    unsigned h = __float_as_uint(x) & 0xFFFFE000u;   // keep top 10 mantissa bits
    hi = h;
    lo = __float_as_uint(x - __uint_as_float(h));
}

__device__ __forceinline__ void mma_tf32(float& c0, float& c1, float& c2, float& c3,
                                         unsigned a0, unsigned a1, unsigned a2, unsigned a3,
                                         unsigned b0, unsigned b1) {
    asm volatile(
        "mma.sync.aligned.m16n8k8.row.col.f32.tf32.tf32.f32 "
        "{%0,%1,%2,%3}, {%4,%5,%6,%7}, {%8,%9}, {%0,%1,%2,%3};\n"
        : "+f"(c0), "+f"(c1), "+f"(c2), "+f"(c3)
        : "r"(a0), "r"(a1), "r"(a2), "r"(a3), "r"(b0), "r"(b1));
}

// ---------------------------------------------------------------------------
// NT GEMM via 3xTF32 tensor cores: C[m,n] = sum_k A[m,k] * W[n,k] (+bias).
// Block tile 128x128, 8 warps, warp tile 32(m)x64(n), k-chunk 32.
// mode 0/1/2: A = x, out -> g_q/g_k/g_v in [B,H,S,Dh] layout
// mode 3:     A = g_att, out -> Cext ([B,S,D]) with bias
// ---------------------------------------------------------------------------
__global__ void __launch_bounds__(256) gemm_tf32(const float* __restrict__ A,
                                                 const float* __restrict__ W,
                                                 const float* __restrict__ bias,
                                                 float* __restrict__ Cext,
                                                 int mode) {
    __shared__ float As[128][36];
    __shared__ float Ws[128][36];

    const int t    = threadIdx.x;
    const int lane = t & 31;
    const int warp = t >> 5;
    const int wm   = warp >> 1;      // 0..3  (m position)
    const int wn   = warp & 1;       // 0..1  (n position)
    const int g    = lane >> 2;      // groupID 0..7
    const int tg   = lane & 3;       // thread in group 0..3

    const int m0 = blockIdx.y * 128;
    const int n0 = blockIdx.x * 128;

    const float* Asrc = (mode == 3) ? g_att : A;
    float* C = (mode == 0) ? g_q : (mode == 1) ? g_k : (mode == 2) ? g_v : Cext;

    float c[2][8][4];
#pragma unroll
    for (int mi = 0; mi < 2; mi++)
#pragma unroll
        for (int ni = 0; ni < 8; ni++)
#pragma unroll
            for (int e = 0; e < 4; e++) c[mi][ni][e] = 0.f;

    for (int k0 = 0; k0 < 1024; k0 += 32) {
        __syncthreads();
#pragma unroll
        for (int i = 0; i < 4; i++) {
            int idx = t + i * 256;
            int row = idx >> 3;
            int fc  = (idx & 7) * 4;
            float4 av = *(const float4*)(Asrc + (size_t)(m0 + row) * 1024 + k0 + fc);
            *(float4*)&As[row][fc] = av;
            float4 wv = *(const float4*)(W + (size_t)(n0 + row) * 1024 + k0 + fc);
            *(float4*)&Ws[row][fc] = wv;
        }
        __syncthreads();

#pragma unroll
        for (int kk = 0; kk < 4; kk++) {
            const int kb = kk * 8;
            unsigned ah[2][4], al[2][4], bh[8][2], bl[8][2];
#pragma unroll
            for (int mi = 0; mi < 2; mi++) {
                const int rb = wm * 32 + mi * 16;
                split_tf32(As[rb + g][kb + tg],          ah[mi][0], al[mi][0]);
                split_tf32(As[rb + g + 8][kb + tg],      ah[mi][1], al[mi][1]);
                split_tf32(As[rb + g][kb + tg + 4],      ah[mi][2], al[mi][2]);
                split_tf32(As[rb + g + 8][kb + tg + 4],  ah[mi][3], al[mi][3]);
            }
#pragma unroll
            for (int ni = 0; ni < 8; ni++) {
                const int nb = wn * 64 + ni * 8;
                split_tf32(Ws[nb + g][kb + tg],     bh[ni][0], bl[ni][0]);
                split_tf32(Ws[nb + g][kb + tg + 4], bh[ni][1], bl[ni][1]);
            }
#pragma unroll
            for (int mi = 0; mi < 2; mi++)
#pragma unroll
                for (int ni = 0; ni < 8; ni++) {
                    mma_tf32(c[mi][ni][0], c[mi][ni][1], c[mi][ni][2], c[mi][ni][3],
                             ah[mi][0], ah[mi][1], ah[mi][2], ah[mi][3],
                             bh[ni][0], bh[ni][1]);
                    mma_tf32(c[mi][ni][0], c[mi][ni][1], c[mi][ni][2], c[mi][ni][3],
                             al[mi][0], al[mi][1], al[mi][2], al[mi][3],
                             bh[ni][0], bh[ni][1]);
                    mma_tf32(c[mi][ni][0], c[mi][ni][1], c[mi][ni][2], c[mi][ni][3],
                             ah[mi][0], ah[mi][1], ah[mi][2], ah[mi][3],
                             bl[ni][0], bl[ni][1]);
                }
        }
    }

    // Epilogue: each c fragment element pair (c0,c1)/(c2,c3) is 2 contiguous n.
#pragma unroll
    for (int mi = 0; mi < 2; mi++) {
#pragma unroll
        for (int ni = 0; ni < 8; ni++) {
            int mA = m0 + wm * 32 + mi * 16 + g;
            int mB = mA + 8;
            int n  = n0 + wn * 64 + ni * 8 + 2 * tg;
            if (mode == 3) {
                float bx = bias[n], by = bias[n + 1];
                *(float2*)(C + (size_t)mA * 1024 + n) =
                    make_float2(c[mi][ni][0] + bx, c[mi][ni][1] + by);
                *(float2*)(C + (size_t)mB * 1024 + n) =
                    make_float2(c[mi][ni][2] + bx, c[mi][ni][3] + by);
            } else {
                int h  = n >> 6;
                int dh = n & 63;
                {
                    int b = mA >> 11, s = mA & 2047;
                    *(float2*)(C + (size_t)((b * HH + h) * SS + s) * DH + dh) =
                        make_float2(c[mi][ni][0], c[mi][ni][1]);
                }
                {
                    int b = mB >> 11, s = mB & 2047;
                    *(float2*)(C + (size_t)((b * HH + h) * SS + s) * DH + dh) =
                        make_float2(c[mi][ni][2], c[mi][ni][3]);
                }
            }
        }
    }
}

// ---------------------------------------------------------------------------
// Flash attention: 1 query row per thread, 128 rows/block, 32-key tiles.
// Reads g_q/g_k/g_v [B,H,S,Dh]; writes g_att [B,S,D].
// ---------------------------------------------------------------------------
__global__ void __launch_bounds__(128) attn128() {
    const int b = blockIdx.z;
    const int h = blockIdx.y;
    const int t = threadIdx.x;
    const int row = blockIdx.x * 128 + t;

    const size_t bh = (size_t)(b * HH + h) * SS;
    const float4* qrow = (const float4*)(g_q + (bh + row) * DH);
    const float4* Kb = (const float4*)(g_k + bh * DH);
    const float4* Vb = (const float4*)(g_v + bh * DH);

    float4 qr[16];
#pragma unroll
    for (int c = 0; c < 16; c++) {
        float4 q4 = qrow[c];
        qr[c] = make_float4(q4.x * 0.125f, q4.y * 0.125f, q4.z * 0.125f, q4.w * 0.125f);
    }
    float4 acc[16];
#pragma unroll
    for (int c = 0; c < 16; c++) acc[c] = make_float4(0.f, 0.f, 0.f, 0.f);

    float mi = -1e30f, li = 0.f;

    __shared__ float4 Ks[32][16];
    __shared__ float4 Vs[32][16];

    for (int kt = 0; kt < SS; kt += 32) {
        __syncthreads();
#pragma unroll
        for (int i = 0; i < 4; i++) {
            int idx = t + i * 128;
            int r = idx >> 4;
            int cc = idx & 15;
            Ks[r][cc] = Kb[(size_t)(kt + r) * 16 + cc];
            Vs[r][cc] = Vb[(size_t)(kt + r) * 16 + cc];
        }
        __syncthreads();

        float sc[32];
        float tmax = mi;
#pragma unroll
        for (int j = 0; j < 32; j++) {
            float4 s4 = make_float4(0.f, 0.f, 0.f, 0.f);
#pragma unroll
            for (int cc = 0; cc < 16; cc++) {
                float4 kk = Ks[j][cc];
                s4.x = fmaf(qr[cc].x, kk.x, s4.x);
                s4.y = fmaf(qr[cc].y, kk.y, s4.y);
                s4.z = fmaf(qr[cc].z, kk.z, s4.z);
                s4.w = fmaf(qr[cc].w, kk.w, s4.w);
            }
            float s = (s4.x + s4.y) + (s4.z + s4.w);
            sc[j] = s;
            tmax = fmaxf(tmax, s);
        }
        float corr = __expf(mi - tmax);
        mi = tmax;
        li *= corr;
#pragma unroll
        for (int cc = 0; cc < 16; cc++) {
            acc[cc].x *= corr; acc[cc].y *= corr;
            acc[cc].z *= corr; acc[cc].w *= corr;
        }
#pragma unroll
        for (int j = 0; j < 32; j++) {
            float p = __expf(sc[j] - mi);
            li += p;
#pragma unroll
            for (int cc = 0; cc < 16; cc++) {
                float4 vv = Vs[j][cc];
                acc[cc].x = fmaf(p, vv.x, acc[cc].x);
                acc[cc].y = fmaf(p, vv.y, acc[cc].y);
                acc[cc].z = fmaf(p, vv.z, acc[cc].z);
                acc[cc].w = fmaf(p, vv.w, acc[cc].w);
            }
        }
    }

    float inv = 1.f / li;
    float4* orow = (float4*)(g_att + ((size_t)b * SS + row) * DD + h * DH);
#pragma unroll
    for (int cc = 0; cc < 16; cc++) {
        orow[cc] = make_float4(acc[cc].x * inv, acc[cc].y * inv,
                               acc[cc].z * inv, acc[cc].w * inv);
    }
}

extern "C" void kernel_launch(void* const* d_in, const int* in_sizes, int n_in,
                              void* d_out, int out_size) {
    const float* x  = (const float*)d_in[0];
    const float* wq = (const float*)d_in[1];
    const float* wk = (const float*)d_in[2];
    const float* wv = (const float*)d_in[3];
    const float* wo = (const float*)d_in[4];
    const float* bo = (const float*)d_in[5];
    float* out = (float*)d_out;

    dim3 gg(DD / 128, MM / 128);   // (8, 32)
    gemm_tf32<<<gg, 256>>>(x, wq, nullptr, nullptr, 0);
    gemm_tf32<<<gg, 256>>>(x, wk, nullptr, nullptr, 1);
    gemm_tf32<<<gg, 256>>>(x, wv, nullptr, nullptr, 2);

    dim3 ga(SS / 128, HH, BB);     // (16, 16, 2)
    attn128<<<ga, 128>>>();

    gemm_tf32<<<gg, 256>>>(nullptr, wo, bo, out, 3);
}

// round 4
// speedup vs baseline: 2.2140x; 1.8730x over previous
#include <cuda_runtime.h>
#include <math.h>

#define BB 2
#define SS 2048
#define DD 1024
#define HH 16
#define DH 64
#define MM (BB * SS)   // 4096

// Scratch: [B,H,S,Dh] for q,k,v ; [B,S,D] for attention output
__device__ float g_q[BB * HH * SS * DH];
__device__ float g_k[BB * HH * SS * DH];
__device__ float g_v[BB * HH * SS * DH];
__device__ float g_att[BB * SS * DD];

// ---------------------------------------------------------------------------
// 3xTF32 split helpers + mma.sync wrapper (m16n8k8 row.col f32.tf32)
// ---------------------------------------------------------------------------
__device__ __forceinline__ void split_tf32(float x, unsigned& hi, unsigned& lo) {
    unsigned h = __float_as_uint(x) & 0xFFFFE000u;   // keep top 10 mantissa bits
    hi = h;
    lo = __float_as_uint(x - __uint_as_float(h));
}

__device__ __forceinline__ unsigned f2tf32(float x) {
    unsigned r;
    asm("cvt.rna.tf32.f32 %0, %1;\n" : "=r"(r) : "f"(x));
    return r;
}

__device__ __forceinline__ void mma_tf32(float& c0, float& c1, float& c2, float& c3,
                                         unsigned a0, unsigned a1, unsigned a2, unsigned a3,
                                         unsigned b0, unsigned b1) {
    asm volatile(
        "mma.sync.aligned.m16n8k8.row.col.f32.tf32.tf32.f32 "
        "{%0,%1,%2,%3}, {%4,%5,%6,%7}, {%8,%9}, {%0,%1,%2,%3};\n"
        : "+f"(c0), "+f"(c1), "+f"(c2), "+f"(c3)
        : "r"(a0), "r"(a1), "r"(a2), "r"(a3), "r"(b0), "r"(b1));
}

// ---------------------------------------------------------------------------
// NT GEMM via 3xTF32 tensor cores: C[m,n] = sum_k A[m,k] * W[n,k] (+bias).
// Block tile 128x128, 8 warps, warp tile 32(m)x64(n), k-chunk 32.
// mode 0: fused QKV. A = x, blockIdx.z picks (Wq->g_q, Wk->g_k, Wv->g_v),
//         output in [B,H,S,Dh] layout.
// mode 3: A = g_att, W = W0 (= wo), out -> Cext ([B,S,D]) with bias.
// ---------------------------------------------------------------------------
__global__ void __launch_bounds__(256) gemm_tf32(const float* __restrict__ A,
                                                 const float* __restrict__ W0,
                                                 const float* __restrict__ W1,
                                                 const float* __restrict__ W2,
                                                 const float* __restrict__ bias,
                                                 float* __restrict__ Cext,
                                                 int mode) {
    __shared__ float As[128][36];
    __shared__ float Ws[128][36];

    const int t    = threadIdx.x;
    const int lane = t & 31;
    const int warp = t >> 5;
    const int wm   = warp >> 1;      // 0..3  (m position)
    const int wn   = warp & 1;       // 0..1  (n position)
    const int g    = lane >> 2;      // groupID 0..7
    const int tg   = lane & 3;       // thread in group 0..3

    const int m0 = blockIdx.y * 128;
    const int n0 = blockIdx.x * 128;
    const int z  = blockIdx.z;

    const float* Asrc = (mode == 3) ? g_att : A;
    const float* W = (mode == 3) ? W0 : (z == 0) ? W0 : (z == 1) ? W1 : W2;
    float* C = (mode == 3) ? Cext : (z == 0) ? g_q : (z == 1) ? g_k : g_v;

    float c[2][8][4];
#pragma unroll
    for (int mi = 0; mi < 2; mi++)
#pragma unroll
        for (int ni = 0; ni < 8; ni++)
#pragma unroll
            for (int e = 0; e < 4; e++) c[mi][ni][e] = 0.f;

    for (int k0 = 0; k0 < 1024; k0 += 32) {
        __syncthreads();
#pragma unroll
        for (int i = 0; i < 4; i++) {
            int idx = t + i * 256;
            int row = idx >> 3;
            int fc  = (idx & 7) * 4;
            float4 av = *(const float4*)(Asrc + (size_t)(m0 + row) * 1024 + k0 + fc);
            *(float4*)&As[row][fc] = av;
            float4 wv = *(const float4*)(W + (size_t)(n0 + row) * 1024 + k0 + fc);
            *(float4*)&Ws[row][fc] = wv;
        }
        __syncthreads();

#pragma unroll
        for (int kk = 0; kk < 4; kk++) {
            const int kb = kk * 8;
            unsigned ah[2][4], al[2][4], bh[8][2], bl[8][2];
#pragma unroll
            for (int mi = 0; mi < 2; mi++) {
                const int rb = wm * 32 + mi * 16;
                split_tf32(As[rb + g][kb + tg],          ah[mi][0], al[mi][0]);
                split_tf32(As[rb + g + 8][kb + tg],      ah[mi][1], al[mi][1]);
                split_tf32(As[rb + g][kb + tg + 4],      ah[mi][2], al[mi][2]);
                split_tf32(As[rb + g + 8][kb + tg + 4],  ah[mi][3], al[mi][3]);
            }
#pragma unroll
            for (int ni = 0; ni < 8; ni++) {
                const int nb = wn * 64 + ni * 8;
                split_tf32(Ws[nb + g][kb + tg],     bh[ni][0], bl[ni][0]);
                split_tf32(Ws[nb + g][kb + tg + 4], bh[ni][1], bl[ni][1]);
            }
#pragma unroll
            for (int mi = 0; mi < 2; mi++)
#pragma unroll
                for (int ni = 0; ni < 8; ni++) {
                    mma_tf32(c[mi][ni][0], c[mi][ni][1], c[mi][ni][2], c[mi][ni][3],
                             ah[mi][0], ah[mi][1], ah[mi][2], ah[mi][3],
                             bh[ni][0], bh[ni][1]);
                    mma_tf32(c[mi][ni][0], c[mi][ni][1], c[mi][ni][2], c[mi][ni][3],
                             al[mi][0], al[mi][1], al[mi][2], al[mi][3],
                             bh[ni][0], bh[ni][1]);
                    mma_tf32(c[mi][ni][0], c[mi][ni][1], c[mi][ni][2], c[mi][ni][3],
                             ah[mi][0], ah[mi][1], ah[mi][2], ah[mi][3],
                             bl[ni][0], bl[ni][1]);
                }
        }
    }

    // Epilogue: each c fragment element pair (c0,c1)/(c2,c3) is 2 contiguous n.
#pragma unroll
    for (int mi = 0; mi < 2; mi++) {
#pragma unroll
        for (int ni = 0; ni < 8; ni++) {
            int mA = m0 + wm * 32 + mi * 16 + g;
            int mB = mA + 8;
            int n  = n0 + wn * 64 + ni * 8 + 2 * tg;
            if (mode == 3) {
                float bx = bias[n], by = bias[n + 1];
                *(float2*)(C + (size_t)mA * 1024 + n) =
                    make_float2(c[mi][ni][0] + bx, c[mi][ni][1] + by);
                *(float2*)(C + (size_t)mB * 1024 + n) =
                    make_float2(c[mi][ni][2] + bx, c[mi][ni][3] + by);
            } else {
                int h  = n >> 6;
                int dh = n & 63;
                {
                    int b = mA >> 11, s = mA & 2047;
                    *(float2*)(C + (size_t)((b * HH + h) * SS + s) * DH + dh) =
                        make_float2(c[mi][ni][0], c[mi][ni][1]);
                }
                {
                    int b = mB >> 11, s = mB & 2047;
                    *(float2*)(C + (size_t)((b * HH + h) * SS + s) * DH + dh) =
                        make_float2(c[mi][ni][2], c[mi][ni][3]);
                }
            }
        }
    }
}

// ---------------------------------------------------------------------------
// Flash attention via tensor cores.
// Block = 64 query rows, 4 warps (16 rows each), 64-key tiles through SMEM.
// QK^T: 3xTF32 split (accurate scores). P*V: single tf32 with RN conversion.
// Reads g_q/g_k/g_v [B,H,S,Dh]; writes g_att [B,S,D].
// ---------------------------------------------------------------------------
__global__ void __launch_bounds__(128) attn_mma() {
    const int b = blockIdx.z;
    const int h = blockIdx.y;
    const int t = threadIdx.x;
    const int warp = t >> 5;
    const int lane = t & 31;
    const int g  = lane >> 2;   // 0..7
    const int tg = lane & 3;    // 0..3
    const int qrow0 = blockIdx.x * 64 + warp * 16;
    const size_t bh = (size_t)(b * HH + h) * SS;

    __shared__ float    Ks[64][68];   // fp32 K tile (stride 68: 4g+tg conflict-free)
    __shared__ unsigned Vs[64][72];   // tf32 V tile (stride 72: 8tg+g conflict-free)
    __shared__ unsigned Ps[64][68];   // tf32 P tile (per-warp 16-row slabs)

    // Q fragments for this warp's 16 rows, pre-scaled and split (persist in regs).
    unsigned qh[8][4], ql[8][4];
    {
        const float* Q = g_q + (bh + qrow0) * DH;
#pragma unroll
        for (int kb = 0; kb < 8; kb++) {
            float a0 = Q[g * DH + kb * 8 + tg] * 0.125f;
            float a1 = Q[(g + 8) * DH + kb * 8 + tg] * 0.125f;
            float a2 = Q[g * DH + kb * 8 + tg + 4] * 0.125f;
            float a3 = Q[(g + 8) * DH + kb * 8 + tg + 4] * 0.125f;
            split_tf32(a0, qh[kb][0], ql[kb][0]);
            split_tf32(a1, qh[kb][1], ql[kb][1]);
            split_tf32(a2, qh[kb][2], ql[kb][2]);
            split_tf32(a3, qh[kb][3], ql[kb][3]);
        }
    }

    float o[8][4];
#pragma unroll
    for (int ni = 0; ni < 8; ni++)
#pragma unroll
        for (int e = 0; e < 4; e++) o[ni][e] = 0.f;
    float mi0 = -1e30f, mi8 = -1e30f, li0 = 0.f, li8 = 0.f;

    for (int kt = 0; kt < SS; kt += 64) {
        __syncthreads();
#pragma unroll
        for (int i = 0; i < 8; i++) {
            int idx = t + i * 128;
            int r = idx >> 4;
            int c = (idx & 15) * 4;
            *(float4*)&Ks[r][c] = *(const float4*)(g_k + (bh + kt + r) * DH + c);
            float4 vv = *(const float4*)(g_v + (bh + kt + r) * DH + c);
            Vs[r][c + 0] = f2tf32(vv.x);
            Vs[r][c + 1] = f2tf32(vv.y);
            Vs[r][c + 2] = f2tf32(vv.z);
            Vs[r][c + 3] = f2tf32(vv.w);
        }
        __syncthreads();

        // S = Q * K^T (3x split), warp computes 16x64 scores.
        float s[8][4];
#pragma unroll
        for (int ni = 0; ni < 8; ni++)
#pragma unroll
            for (int e = 0; e < 4; e++) s[ni][e] = 0.f;

#pragma unroll
        for (int kb = 0; kb < 8; kb++) {
#pragma unroll
            for (int ni = 0; ni < 8; ni++) {
                unsigned b0h, b0l, b1h, b1l;
                split_tf32(Ks[ni * 8 + g][kb * 8 + tg],     b0h, b0l);
                split_tf32(Ks[ni * 8 + g][kb * 8 + tg + 4], b1h, b1l);
                mma_tf32(s[ni][0], s[ni][1], s[ni][2], s[ni][3],
                         qh[kb][0], qh[kb][1], qh[kb][2], qh[kb][3], b0h, b1h);
                mma_tf32(s[ni][0], s[ni][1], s[ni][2], s[ni][3],
                         ql[kb][0], ql[kb][1], ql[kb][2], ql[kb][3], b0h, b1h);
                mma_tf32(s[ni][0], s[ni][1], s[ni][2], s[ni][3],
                         qh[kb][0], qh[kb][1], qh[kb][2], qh[kb][3], b0l, b1l);
            }
        }

        // Online softmax. Rows: g (elements 0,1) and g+8 (elements 2,3).
        float t0 = mi0, t8 = mi8;
#pragma unroll
        for (int ni = 0; ni < 8; ni++) {
            t0 = fmaxf(t0, fmaxf(s[ni][0], s[ni][1]));
            t8 = fmaxf(t8, fmaxf(s[ni][2], s[ni][3]));
        }
        t0 = fmaxf(t0, __shfl_xor_sync(0xffffffffu, t0, 1));
        t0 = fmaxf(t0, __shfl_xor_sync(0xffffffffu, t0, 2));
        t8 = fmaxf(t8, __shfl_xor_sync(0xffffffffu, t8, 1));
        t8 = fmaxf(t8, __shfl_xor_sync(0xffffffffu, t8, 2));

        float c0 = __expf(mi0 - t0);
        float c8 = __expf(mi8 - t8);
        mi0 = t0; mi8 = t8;
        li0 *= c0; li8 *= c8;

        float rs0 = 0.f, rs8 = 0.f;
#pragma unroll
        for (int ni = 0; ni < 8; ni++) {
            o[ni][0] *= c0; o[ni][1] *= c0;
            o[ni][2] *= c8; o[ni][3] *= c8;
            float p0 = __expf(s[ni][0] - mi0);
            float p1 = __expf(s[ni][1] - mi0);
            float p2 = __expf(s[ni][2] - mi8);
            float p3 = __expf(s[ni][3] - mi8);
            rs0 += p0 + p1;
            rs8 += p2 + p3;
            Ps[warp * 16 + g][ni * 8 + 2 * tg]         = f2tf32(p0);
            Ps[warp * 16 + g][ni * 8 + 2 * tg + 1]     = f2tf32(p1);
            Ps[warp * 16 + 8 + g][ni * 8 + 2 * tg]     = f2tf32(p2);
            Ps[warp * 16 + 8 + g][ni * 8 + 2 * tg + 1] = f2tf32(p3);
        }
        li0 += rs0; li8 += rs8;
        __syncwarp();

        // O += P * V (single tf32; errors are RN zero-mean and average out).
#pragma unroll
        for (int kb = 0; kb < 8; kb++) {
            unsigned a0 = Ps[warp * 16 + g][kb * 8 + tg];
            unsigned a1 = Ps[warp * 16 + 8 + g][kb * 8 + tg];
            unsigned a2 = Ps[warp * 16 + g][kb * 8 + tg + 4];
            unsigned a3 = Ps[warp * 16 + 8 + g][kb * 8 + tg + 4];
#pragma unroll
            for (int ni = 0; ni < 8; ni++) {
                mma_tf32(o[ni][0], o[ni][1], o[ni][2], o[ni][3],
                         a0, a1, a2, a3,
                         Vs[kb * 8 + tg][ni * 8 + g], Vs[kb * 8 + tg + 4][ni * 8 + g]);
            }
        }
        __syncwarp();
    }

    li0 += __shfl_xor_sync(0xffffffffu, li0, 1);
    li0 += __shfl_xor_sync(0xffffffffu, li0, 2);
    li8 += __shfl_xor_sync(0xffffffffu, li8, 1);
    li8 += __shfl_xor_sync(0xffffffffu, li8, 2);
    float inv0 = 1.f / li0;
    float inv8 = 1.f / li8;

    float* O0 = g_att + ((size_t)b * SS + qrow0 + g) * DD + h * DH;
    float* O8 = g_att + ((size_t)b * SS + qrow0 + 8 + g) * DD + h * DH;
#pragma unroll
    for (int ni = 0; ni < 8; ni++) {
        *(float2*)(O0 + ni * 8 + 2 * tg) = make_float2(o[ni][0] * inv0, o[ni][1] * inv0);
        *(float2*)(O8 + ni * 8 + 2 * tg) = make_float2(o[ni][2] * inv8, o[ni][3] * inv8);
    }
}

extern "C" void kernel_launch(void* const* d_in, const int* in_sizes, int n_in,
                              void* d_out, int out_size) {
    const float* x  = (const float*)d_in[0];
    const float* wq = (const float*)d_in[1];
    const float* wk = (const float*)d_in[2];
    const float* wv = (const float*)d_in[3];
    const float* wo = (const float*)d_in[4];
    const float* bo = (const float*)d_in[5];
    float* out = (float*)d_out;

    dim3 gqkv(DD / 128, MM / 128, 3);   // (8, 32, 3) fused Q/K/V projections
    gemm_tf32<<<gqkv, 256>>>(x, wq, wk, wv, nullptr, nullptr, 0);

    dim3 ga(SS / 64, HH, BB);           // (32, 16, 2)
    attn_mma<<<ga, 128>>>();

    dim3 go(DD / 128, MM / 128, 1);
    gemm_tf32<<<go, 256>>>(nullptr, wo, nullptr, nullptr, bo, out, 3);
}